// round 1
// baseline (speedup 1.0000x reference)
#include <cuda_runtime.h>

// Problem constants
#define N_NODES 4096
#define F_IN    256
#define F_OUT   256
#define H_HEADS 4
#define D_HEAD  64
#define C_OUT   256   // H_HEADS * D_HEAD

#define JSPLIT  2
#define TI      64
#define TJ      16

// ---------------- scratch (no cudaMalloc allowed) ----------------
__device__ __align__(16) float g_h [N_NODES * F_OUT];          // projected features
__device__ __align__(16) float g_S [N_NODES * H_HEADS];        // attn_src
__device__ __align__(16) float g_T [N_NODES * H_HEADS];        // attn_dst
__device__ __align__(16) float g_F1[N_NODES * H_HEADS];        // exp(asrc)
__device__ __align__(16) float g_F2[N_NODES * H_HEADS];        // exp(0.2*asrc)
__device__ __align__(16) float g_E1[N_NODES * H_HEADS];        // exp(adst)
__device__ __align__(16) float g_E2[N_NODES * H_HEADS];        // exp(0.2*adst)
__device__ __align__(16) float g_U [JSPLIT][N_NODES * C_OUT];  // partial weighted sums
__device__ __align__(16) float g_Z [JSPLIT][N_NODES * H_HEADS];// partial softmax denominators

// ---------------- packed f32x2 helpers ----------------
__device__ __forceinline__ void fma2(unsigned long long& acc,
                                     unsigned long long a,
                                     unsigned long long b) {
    asm("fma.rn.f32x2 %0, %1, %2, %0;" : "+l"(acc) : "l"(a), "l"(b));
}
__device__ __forceinline__ unsigned long long pack2(float lo, float hi) {
    unsigned long long r;
    asm("mov.b64 %0, {%1, %2};" : "=l"(r) : "f"(lo), "f"(hi));
    return r;
}
__device__ __forceinline__ void unpack2(unsigned long long v, float& lo, float& hi) {
    asm("mov.b64 {%0, %1}, %2;" : "=f"(lo), "=f"(hi) : "l"(v));
}

// ================= K1: h = x @ W^T  (4096x256x256) =================
__global__ void __launch_bounds__(256) k1_gemm(const float* __restrict__ x,
                                               const float* __restrict__ W) {
    __shared__ float xs[16][68];
    __shared__ float ws[16][68];
    const int tid = threadIdx.x;
    const int m0 = blockIdx.x * 64;
    const int n0 = blockIdx.y * 64;
    const int tr = tid >> 4;      // 0..15
    const int tc = tid & 15;      // 0..15
    const int lm  = tid >> 2;     // 0..63  (stage row)
    const int lk4 = (tid & 3) << 2;

    float acc[4][4];
#pragma unroll
    for (int r = 0; r < 4; r++)
#pragma unroll
        for (int c = 0; c < 4; c++) acc[r][c] = 0.f;

    for (int k0 = 0; k0 < F_IN; k0 += 16) {
        float4 xv = *(const float4*)(x + (size_t)(m0 + lm) * F_IN + k0 + lk4);
        float4 wv = *(const float4*)(W + (size_t)(n0 + lm) * F_IN + k0 + lk4);
        __syncthreads();
        xs[lk4 + 0][lm] = xv.x; xs[lk4 + 1][lm] = xv.y;
        xs[lk4 + 2][lm] = xv.z; xs[lk4 + 3][lm] = xv.w;
        ws[lk4 + 0][lm] = wv.x; ws[lk4 + 1][lm] = wv.y;
        ws[lk4 + 2][lm] = wv.z; ws[lk4 + 3][lm] = wv.w;
        __syncthreads();
#pragma unroll
        for (int kk = 0; kk < 16; kk++) {
            float xa[4], wb[4];
#pragma unroll
            for (int r = 0; r < 4; r++) xa[r] = xs[kk][tr * 4 + r];
#pragma unroll
            for (int c = 0; c < 4; c++) wb[c] = ws[kk][tc * 4 + c];
#pragma unroll
            for (int r = 0; r < 4; r++)
#pragma unroll
                for (int c = 0; c < 4; c++) acc[r][c] += xa[r] * wb[c];
        }
    }
#pragma unroll
    for (int r = 0; r < 4; r++) {
        float4 o = make_float4(acc[r][0], acc[r][1], acc[r][2], acc[r][3]);
        *(float4*)(g_h + (size_t)(m0 + tr * 4 + r) * F_OUT + n0 + tc * 4) = o;
    }
}

// ============ K2: per-node logits + exp factor tables ============
__global__ void __launch_bounds__(256) k2_logits(const float* __restrict__ a_src,
                                                 const float* __restrict__ a_dst) {
    const int idx = blockIdx.x * 256 + threadIdx.x;   // 0..16383
    const int n  = idx >> 2;
    const int hh = idx & 3;
    const float* hp = g_h + (size_t)n * C_OUT + hh * D_HEAD;
    const float* as = a_src + hh * D_HEAD;
    const float* ad = a_dst + hh * D_HEAD;
    float s = 0.f, t = 0.f;
#pragma unroll
    for (int d = 0; d < D_HEAD; d += 4) {
        float4 hv = *(const float4*)(hp + d);
        float4 av = *(const float4*)(as + d);
        float4 dv = *(const float4*)(ad + d);
        s += hv.x * av.x + hv.y * av.y + hv.z * av.z + hv.w * av.w;
        t += hv.x * dv.x + hv.y * dv.y + hv.z * dv.z + hv.w * dv.w;
    }
    g_S[idx]  = s;
    g_T[idx]  = t;
    g_F1[idx] = expf(s);
    g_F2[idx] = expf(0.2f * s);
    g_E1[idx] = expf(t);
    g_E2[idx] = expf(0.2f * t);
}

// ======= K3: fused masked-softmax-weight + aggregation (single adj pass) =======
// CTA: TI=64 rows i, all 256 output cols, j-range = N/JSPLIT.
// Accumulates U[i,c] (unnormalized) and Z[i,h] simultaneously.
__global__ void __launch_bounds__(256, 1) k3_agg(const float* __restrict__ adj) {
    __shared__ __align__(16) float hs [TJ * 256];      // permuted h tile
    __shared__ __align__(16) float wsm[TJ * 256];      // [jj][h*64 + i]
    __shared__ float adj_s[TI][TJ + 1];
    __shared__ float Ts [TJ][4];
    __shared__ float E1s[TJ][4];
    __shared__ float E2s[TJ][4];

    const int tid = threadIdx.x;
    const int i0 = blockIdx.x * TI;
    const int split = blockIdx.y;
    const int jbeg = split * (N_NODES / JSPLIT);
    const int jend = jbeg + (N_NODES / JSPLIT);

    // --- weight-compute role: thread -> (i = tid&63, h = tid>>6) ---
    const int hw = tid >> 6;
    const int iw = tid & 63;
    const float S_i  = g_S [(i0 + iw) * 4 + hw];
    const float F1_i = g_F1[(i0 + iw) * 4 + hw];
    const float F2_i = g_F2[(i0 + iw) * 4 + hw];
    float Zreg = 0.f;

    // --- FMA role: thread -> rows [tr*8..+7], cols [tc*8..+7] ---
    const int tr = tid >> 5;       // 0..7
    const int tc = tid & 31;       // 0..31
    const int hc = tc >> 3;        // head of this col block

    unsigned long long acc[8][4];
#pragma unroll
    for (int r = 0; r < 8; r++)
#pragma unroll
        for (int p = 0; p < 4; p++) acc[r][p] = 0ull;

    const int ar = tid >> 2;           // adj stage row 0..63
    const int ac = (tid & 3) << 2;     // adj stage col 0,4,8,12

    for (int jb = jbeg; jb < jend; jb += TJ) {
        __syncthreads();   // previous tile fully consumed

        // stage adj tile [64][16]
        {
            float4 av = *(const float4*)(adj + (size_t)(i0 + ar) * N_NODES + jb + ac);
            adj_s[ar][ac + 0] = av.x; adj_s[ar][ac + 1] = av.y;
            adj_s[ar][ac + 2] = av.z; adj_s[ar][ac + 3] = av.w;
        }
        // stage per-j exp tables
        if (tid < 64) {
            const int jj = tid >> 2, h2 = tid & 3;
            const int gi = (jb + jj) * 4 + h2;
            Ts [jj][h2] = g_T [gi];
            E1s[jj][h2] = g_E1[gi];
            E2s[jj][h2] = g_E2[gi];
        }
        // stage h tile with lo/hi split layout (conflict-free LDS.128 reads)
#pragma unroll
        for (int it = 0; it < 4; it++) {
            const int lin = it * 1024 + tid * 4;
            const int jj = lin >> 8;
            const int c  = lin & 255;
            float4 hv = *(const float4*)(g_h + (size_t)(jb + jj) * C_OUT + c);
            const int off = jj * 256 + ((c >> 2) & 1) * 128 + (c >> 3) * 4;
            *(float4*)(hs + off) = hv;
        }
        __syncthreads();

        // compute masked softmax weights w = adj * p, accumulate Z = sum p
#pragma unroll
        for (int jj = 0; jj < TJ; jj++) {
            const float t = S_i + Ts[jj][hw];
            const float p = (t >= 0.f) ? F1_i * E1s[jj][hw] : F2_i * E2s[jj][hw];
            const float a = adj_s[iw][jj];
            float w = 0.f;
            if (a > 0.f) { Zreg += p; w = a * p; }
            wsm[jj * 256 + hw * 64 + iw] = w;
        }
        __syncthreads();

        // outer-product accumulation: U[i, c] += w[i] * h[j, c]
#pragma unroll
        for (int jj = 0; jj < TJ; jj++) {
            const ulonglong2 hlo = *(const ulonglong2*)(hs + jj * 256 + tc * 4);
            const ulonglong2 hhi = *(const ulonglong2*)(hs + jj * 256 + 128 + tc * 4);
            const float4 w0 = *(const float4*)(wsm + jj * 256 + hc * 64 + tr * 8);
            const float4 w1 = *(const float4*)(wsm + jj * 256 + hc * 64 + tr * 8 + 4);
            const float wv[8] = {w0.x, w0.y, w0.z, w0.w, w1.x, w1.y, w1.z, w1.w};
#pragma unroll
            for (int r = 0; r < 8; r++) {
                const unsigned long long wp = pack2(wv[r], wv[r]);
                fma2(acc[r][0], wp, hlo.x);
                fma2(acc[r][1], wp, hlo.y);
                fma2(acc[r][2], wp, hhi.x);
                fma2(acc[r][3], wp, hhi.y);
            }
        }
    }

    // write partial Z and U
    g_Z[split][(i0 + iw) * 4 + hw] = Zreg;
#pragma unroll
    for (int r = 0; r < 8; r++) {
        const int row = i0 + tr * 8 + r;
        float a0, a1, a2, a3, a4, a5, a6, a7;
        unpack2(acc[r][0], a0, a1);
        unpack2(acc[r][1], a2, a3);
        unpack2(acc[r][2], a4, a5);
        unpack2(acc[r][3], a6, a7);
        *(float4*)(g_U[split] + (size_t)row * C_OUT + tc * 8)     = make_float4(a0, a1, a2, a3);
        *(float4*)(g_U[split] + (size_t)row * C_OUT + tc * 8 + 4) = make_float4(a4, a5, a6, a7);
    }
}

// ============ K4: reduce splits + normalize (+ nan_to_num) ============
__global__ void __launch_bounds__(256) k4_final(float* __restrict__ out) {
    const int n = blockIdx.x;
    const int c = threadIdx.x;
    const int hh = c >> 6;
    const float Z = g_Z[0][n * 4 + hh] + g_Z[1][n * 4 + hh];
    const float u = g_U[0][n * C_OUT + c] + g_U[1][n * C_OUT + c];
    out[n * C_OUT + c] = (Z > 0.f) ? (u / Z) : 0.f;
}

// ---------------- launch ----------------
extern "C" void kernel_launch(void* const* d_in, const int* in_sizes, int n_in,
                              void* d_out, int out_size) {
    const float* x     = (const float*)d_in[0];
    const float* adj   = (const float*)d_in[1];
    const float* W     = (const float*)d_in[2];
    const float* a_src = (const float*)d_in[3];
    const float* a_dst = (const float*)d_in[4];
    float* out = (float*)d_out;

    k1_gemm<<<dim3(N_NODES / 64, F_OUT / 64), 256>>>(x, W);
    k2_logits<<<(N_NODES * H_HEADS) / 256, 256>>>(a_src, a_dst);
    k3_agg<<<dim3(N_NODES / TI, JSPLIT), 256>>>(adj);
    k4_final<<<N_NODES, 256>>>(out);
}